// round 10
// baseline (speedup 1.0000x reference)
#include <cuda_runtime.h>
#include <cuda_fp16.h>
#include <stdint.h>
#include <math.h>

#define HID   1024
#define BATCH 4096
#define KPS   256
#define G4H   4096

#define BM 128
#define BN 128
#define BK 64
#define NS 3
#define A_BYTES     (BM * BK * 2)          // 16 KB
#define STAGE_BYTES (2 * A_BYTES)          // 32 KB
#define SMEM_SZ     (NS * STAGE_BYTES)     // 96 KB

// ===========================================================================
// Scratch (__device__ globals; sanctioned no-alloc mechanism)
// ===========================================================================
#define MEL (1024 * 1024)
__device__ __align__(128) __half g_fp16[34 * MEL];   // 68 MB fp16 arena
__device__ float g_bias_perm[3 * G4H];

// arena offsets (half elements)
#define O_X     (0 * MEL)
#define O_H0    (1 * MEL)
#define O_H1    (5 * MEL)
#define O_H2    (9 * MEL)
#define O_WIH1  (13 * MEL)
#define O_WHH1  (14 * MEL)
#define O_WIH2  (18 * MEL)
#define O_WHH2  (22 * MEL)
#define O_WIH3  (26 * MEL)
#define O_WHH3  (30 * MEL)

// ===========================================================================
// Helpers
// ===========================================================================
__device__ __forceinline__ uint32_t smem_u32(const void* p) {
    uint32_t a;
    asm("{ .reg .u64 t; cvta.to.shared.u64 t, %1; cvt.u32.u64 %0, t; }" : "=r"(a) : "l"(p));
    return a;
}
__device__ __forceinline__ void cp_async16(uint32_t dst, const void* src) {
    asm volatile("cp.async.cg.shared.global [%0], [%1], 16;" :: "r"(dst), "l"(src));
}
__device__ __forceinline__ void ldsm_x4(uint32_t* r, uint32_t addr) {
    asm volatile("ldmatrix.sync.aligned.m8n8.x4.shared.b16 {%0,%1,%2,%3}, [%4];"
        : "=r"(r[0]), "=r"(r[1]), "=r"(r[2]), "=r"(r[3]) : "r"(addr));
}
__device__ __forceinline__ void mma16816(float* d, const uint32_t* a, uint32_t b0, uint32_t b1) {
    asm volatile("mma.sync.aligned.m16n8k16.row.col.f32.f16.f16.f32 "
        "{%0,%1,%2,%3}, {%4,%5,%6,%7}, {%8,%9}, {%0,%1,%2,%3};"
        : "+f"(d[0]), "+f"(d[1]), "+f"(d[2]), "+f"(d[3])
        : "r"(a[0]), "r"(a[1]), "r"(a[2]), "r"(a[3]), "r"(b0), "r"(b1));
}
__device__ __forceinline__ float sigmoidf_(float x) { return 1.0f / (1.0f + __expf(-x)); }

// ===========================================================================
// Combined fp32->fp16 conversion, 9 jobs, one launch.
// Weight jobs (0-5) apply the gate-interleave ROW PERMUTATION:
//   out row n = 4*j+g  <-  src row g*HID+j      (lgK4 = log2(K/4))
// h-state jobs (6-8) are plain converts (lgK4 = 0).
// ===========================================================================
struct CvtJobs {
    const float4* src[9];
    __half2* dst[9];
    int n4[9];
    int lgK4[9];   // 0 = no permute; else log2(K/4)
};
#define CJ0_BLK 64
#define CJB_BLK 160
#define CVT_GRID (CJ0_BLK + 8 * CJB_BLK)   // 1344

__global__ void k_cvt(CvtJobs J) {
    int bid = blockIdx.x;
    int job, lb, nb;
    if (bid < CJ0_BLK) { job = 0; lb = bid; nb = CJ0_BLK; }
    else { job = 1 + (bid - CJ0_BLK) / CJB_BLK; lb = (bid - CJ0_BLK) % CJB_BLK; nb = CJB_BLK; }
    const float4* __restrict__ src = J.src[job];
    __half2* __restrict__ dst = J.dst[job];
    const int n4 = J.n4[job];
    const int lg = J.lgK4[job];
    const int stride = nb * blockDim.x;
    if (lg == 0) {
        for (int i = lb * blockDim.x + threadIdx.x; i < n4; i += stride) {
            float4 v = src[i];
            dst[2 * i + 0] = __floats2half2_rn(v.x, v.y);
            dst[2 * i + 1] = __floats2half2_rn(v.z, v.w);
        }
    } else {
        const int msk = (1 << lg) - 1;
        for (int i = lb * blockDim.x + threadIdx.x; i < n4; i += stride) {
            int n = i >> lg, kc = i & msk;
            int g = n & 3, j = n >> 2;
            float4 v = src[(((size_t)g * HID + j) << lg) + kc];
            dst[2 * i + 0] = __floats2half2_rn(v.x, v.y);
            dst[2 * i + 1] = __floats2half2_rn(v.z, v.w);
        }
    }
}

// Combined bias perm: out[l][4j+g] = b_ih[l][g*HID+j] + b_hh[l][g*HID+j]
struct BiasJobs { const float* bih[3]; const float* bhh[3]; };
__global__ void k_bias_perm(BiasJobs J, float* __restrict__ out) {
    int idx = blockIdx.x * blockDim.x + threadIdx.x;   // 0..3*4096
    int l = idx >> 12, n = idx & 4095;
    int g = n & 3, j = n >> 2;
    out[idx] = J.bih[l][g * HID + j] + J.bhh[l][g * HID + j];
}

// ===========================================================================
// Embedding SGEMM (fp32), 64x64 tiles, register double-buffered gmem loads.
// Fused fp16 epilogue.
// ===========================================================================
__global__ void __launch_bounds__(256)
emb_gemm_cvt(const float* __restrict__ A1, const float* __restrict__ W1,
             const float* __restrict__ bias1, __half* __restrict__ C16)
{
    const int K1 = KPS, N = KPS;
    __shared__ float As[16][64];
    __shared__ float Bs[16][64];
    const int tid = threadIdx.x;
    const int m0 = blockIdx.y * 64;
    const int n0 = blockIdx.x * 64;
    const int ty = tid >> 4, tx = tid & 15;
    float acc[4][4];
#pragma unroll
    for (int i = 0; i < 4; i++)
#pragma unroll
        for (int j = 0; j < 4; j++) acc[i][j] = 0.0f;

    const int lrow = tid >> 2, lcol4 = (tid & 3) * 4;
    float4 av = *(const float4*)(A1 + (size_t)(m0 + lrow) * K1 + lcol4);
    float4 wv = *(const float4*)(W1 + (size_t)(n0 + lrow) * K1 + lcol4);

    for (int k0 = 0; k0 < K1; k0 += 16) {
        As[lcol4 + 0][lrow] = av.x; As[lcol4 + 1][lrow] = av.y;
        As[lcol4 + 2][lrow] = av.z; As[lcol4 + 3][lrow] = av.w;
        Bs[lcol4 + 0][lrow] = wv.x; Bs[lcol4 + 1][lrow] = wv.y;
        Bs[lcol4 + 2][lrow] = wv.z; Bs[lcol4 + 3][lrow] = wv.w;
        __syncthreads();
        if (k0 + 16 < K1) {
            av = *(const float4*)(A1 + (size_t)(m0 + lrow) * K1 + k0 + 16 + lcol4);
            wv = *(const float4*)(W1 + (size_t)(n0 + lrow) * K1 + k0 + 16 + lcol4);
        }
#pragma unroll
        for (int k = 0; k < 16; k++) {
            float ar[4], br[4];
#pragma unroll
            for (int i = 0; i < 4; i++) ar[i] = As[k][ty * 4 + i];
#pragma unroll
            for (int j = 0; j < 4; j++) br[j] = Bs[k][tx * 4 + j];
#pragma unroll
            for (int i = 0; i < 4; i++)
#pragma unroll
                for (int j = 0; j < 4; j++)
                    acc[i][j] = fmaf(ar[i], br[j], acc[i][j]);
        }
        __syncthreads();
    }
#pragma unroll
    for (int i = 0; i < 4; i++) {
        int m = m0 + ty * 4 + i;
        int n = n0 + tx * 4;
#pragma unroll
        for (int j = 0; j < 4; j++)
            C16[(size_t)m * N + n + j] = __float2half_rn(acc[i][j] + bias1[n + j]);
    }
}

// ===========================================================================
// Fused LSTM GEMM (HMMA fp16): CTA 128x128, 4 warps (2m x 2n), warp tile
// 64x64, 128 threads => reg ceiling 255 per thread, 2 CTAs/SM. Explicit
// fragment DOUBLE-BUFFERING hides ldsm latency at low warp count.
// smem reads drop to 64KB/stage/CTA -> tensor pipe becomes the binder.
// ===========================================================================
struct SegInfo { const __half *A, *B; int K, ldA, ldB; };
struct LstmArgs {
    SegInfo seg[2];
    const float* bias;     // gate-interleaved [4096]: 4j+g
    const float* c_old;
    float* h_out; float* h_out2; float* c_out;
};
struct AllArgs { LstmArgs l[3]; };

__global__ void __launch_bounds__(128) lstm_gemm(AllArgs args)
{
    extern __shared__ __align__(1024) char smem[];
    const LstmArgs& L = args.l[blockIdx.z];
    const int m0   = blockIdx.y * BM;
    const int n0   = blockIdx.x * BN;      // permuted-weight row base
    const int jb32 = n0 >> 2;
    const int tid  = threadIdx.x;
    const int lane = tid & 31, wid = tid >> 5;
    const int warp_m = wid & 1, warp_n = wid >> 1;   // 2 x 2
    const int wm0 = warp_m * 64, wn0 = warp_n * 64;
    const uint32_t sb = smem_u32(smem);

    const int k1 = L.seg[0].K >> 6;
    const int KT = k1 + (L.seg[1].K >> 6);

    float acc[32][4];
#pragma unroll
    for (int i = 0; i < 32; i++)
#pragma unroll
        for (int j = 0; j < 4; j++) acc[i][j] = 0.0f;

    auto load_stage = [&](int t) {
        const int s = t % NS;
        const int seg = (t >= k1) ? 1 : 0;
        const int k0 = (t - (seg ? k1 : 0)) << 6;
        const __half* Ap = L.seg[seg].A; const int ldA = L.seg[seg].ldA;
        const __half* Bp = L.seg[seg].B; const int ldB = L.seg[seg].ldB;
        const uint32_t sa = sb + s * STAGE_BYTES;
        const uint32_t sB = sa + A_BYTES;
#pragma unroll
        for (int i = 0; i < 8; i++) {
            int lin = tid + (i << 7);
            int r = lin >> 3, kc = lin & 7;
            cp_async16(sa + r * 128 + ((kc ^ (r & 7)) << 4),
                       Ap + (size_t)(m0 + r) * ldA + k0 + (kc << 3));
        }
#pragma unroll
        for (int i = 0; i < 8; i++) {
            int lin = tid + (i << 7);
            int n = lin >> 3, kc = lin & 7;
            cp_async16(sB + n * 128 + ((kc ^ (n & 7)) << 4),
                       Bp + (size_t)(n0 + n) * ldB + k0 + (kc << 3));
        }
        asm volatile("cp.async.commit_group;" ::: "memory");
    };

    // prologue: NS-1 stages ahead
    for (int s = 0; s < NS - 1; s++) load_stage(s);

    // persistent double-buffered fragments
    uint32_t afr[2][4][4];   // [buf][mt][regs]
    uint32_t bfr[2][4][4];   // [buf][op][regs]

    for (int t = 0; t < KT; t++) {
        asm volatile("cp.async.wait_group %0;" :: "n"(NS - 2) : "memory");
        __syncthreads();
        const uint32_t sa = sb + (t % NS) * STAGE_BYTES;
        const uint32_t sB = sa + A_BYTES;

#define LDF(kk, buf) do { \
    _Pragma("unroll") \
    for (int mt = 0; mt < 4; mt++) { \
        int row = wm0 + mt * 16 + (lane & 15); \
        int kc = (kk) * 2 + (lane >> 4); \
        ldsm_x4(afr[buf][mt], sa + row * 128 + ((kc ^ (row & 7)) << 4)); \
    } \
    _Pragma("unroll") \
    for (int op = 0; op < 4; op++) { \
        int n = wn0 + op * 16 + ((lane >> 4) << 3) + (lane & 7); \
        int kc = (kk) * 2 + ((lane >> 3) & 1); \
        ldsm_x4(bfr[buf][op], sB + n * 128 + ((kc ^ (n & 7)) << 4)); \
    } \
} while (0)

        LDF(0, 0);
        // issue next stage's cp.asyncs while kk=0 frags land
        if (t + NS - 1 < KT) load_stage(t + NS - 1);

#pragma unroll
        for (int kk = 0; kk < 4; kk++) {
            const int cur = kk & 1;
            if (kk < 3) LDF(kk + 1, cur ^ 1);
#pragma unroll
            for (int op = 0; op < 4; op++) {
#pragma unroll
                for (int mt = 0; mt < 4; mt++) {
                    mma16816(acc[mt * 8 + op * 2 + 0], afr[cur][mt], bfr[cur][op][0], bfr[cur][op][1]);
                    mma16816(acc[mt * 8 + op * 2 + 1], afr[cur][mt], bfr[cur][op][2], bfr[cur][op][3]);
                }
            }
        }
#undef LDF
    }

    // --------------------------------------------------------------
    // Fused LSTM epilogue (gate-interleaved cols; shfl pairs (i,f)/(g,o)).
    // --------------------------------------------------------------
    const float* __restrict__ bias = L.bias;
    const float* __restrict__ cold = L.c_old;
    const int qid = lane & 3;
#pragma unroll
    for (int mt = 0; mt < 4; mt++) {
#pragma unroll
        for (int oct = 0; oct < 8; oct++) {
            float c0 = acc[mt * 8 + oct][0], c1 = acc[mt * 8 + oct][1];
            float c2 = acc[mt * 8 + oct][2], c3 = acc[mt * 8 + oct][3];
            float o0 = __shfl_xor_sync(0xffffffffu, c0, 1);
            float o1 = __shfl_xor_sync(0xffffffffu, c1, 1);
            float o2 = __shfl_xor_sync(0xffffffffu, c2, 1);
            float o3 = __shfl_xor_sync(0xffffffffu, c3, 1);
            float gi, gf, gg, go;
            int r;
            if ((lane & 1) == 0) {      // even lane: owns (i,f), receives (g,o); row+8
                gi = c2; gf = c3; gg = o2; go = o3;
                r = wm0 + mt * 16 + (lane >> 2) + 8;
            } else {                    // odd lane: owns (g,o), receives (i,f); row
                gi = o0; gf = o1; gg = c0; go = c1;
                r = wm0 + mt * 16 + (lane >> 2);
            }
            const int j = jb32 + warp_n * 16 + oct * 2 + (qid >> 1);
            const float4 bb = *(const float4*)(bias + 4 * j);
            gi = sigmoidf_(gi + bb.x);
            gf = sigmoidf_(gf + bb.y);
            gg = tanhf(gg + bb.z);
            go = sigmoidf_(go + bb.w);
            const size_t idx = (size_t)(m0 + r) * HID + j;
            float cn = gf * cold[idx] + gi * gg;
            float hn = go * tanhf(cn);
            L.c_out[idx] = cn;
            L.h_out[idx] = hn;
            if (L.h_out2) L.h_out2[idx] = hn;
        }
    }
}

// ===========================================================================
extern "C" void kernel_launch(void* const* d_in, const int* in_sizes, int n_in,
                              void* d_out, int out_size)
{
    const float* kps   = (const float*)d_in[0];
    const float* h0    = (const float*)d_in[1];
    const float* h1    = (const float*)d_in[2];
    const float* h2    = (const float*)d_in[3];
    const float* c0    = (const float*)d_in[4];
    const float* c1    = (const float*)d_in[5];
    const float* c2    = (const float*)d_in[6];
    const float* W_emb = (const float*)d_in[7];
    const float* b_emb = (const float*)d_in[8];
    const float* w_ih1 = (const float*)d_in[9];
    const float* w_hh1 = (const float*)d_in[10];
    const float* b_ih1 = (const float*)d_in[11];
    const float* b_hh1 = (const float*)d_in[12];
    const float* w_ih2 = (const float*)d_in[13];
    const float* w_hh2 = (const float*)d_in[14];
    const float* b_ih2 = (const float*)d_in[15];
    const float* b_hh2 = (const float*)d_in[16];
    const float* w_ih3 = (const float*)d_in[17];
    const float* w_hh3 = (const float*)d_in[18];
    const float* b_ih3 = (const float*)d_in[19];
    const float* b_hh3 = (const float*)d_in[20];

    float* out = (float*)d_out;
    const size_t S = (size_t)BATCH * HID;
    float* out_h2n_a = out + 0 * S;
    float* out_h0n   = out + 1 * S;
    float* out_h1n   = out + 2 * S;
    float* out_h2n_b = out + 3 * S;
    float* out_c0n   = out + 4 * S;
    float* out_c1n   = out + 5 * S;
    float* out_c2n   = out + 6 * S;

    __half* hp = nullptr;
    float* biasp = nullptr;
    cudaGetSymbolAddress((void**)&hp, g_fp16);
    cudaGetSymbolAddress((void**)&biasp, g_bias_perm);

    // --- all fp32->fp16 conversions (one launch, 9 jobs; weights permuted) ---
    CvtJobs C;
    C.src[0] = (const float4*)w_ih1; C.dst[0] = (__half2*)(hp + O_WIH1); C.n4[0] = (G4H * KPS) / 4; C.lgK4[0] = 6;
    C.src[1] = (const float4*)w_hh1; C.dst[1] = (__half2*)(hp + O_WHH1); C.n4[1] = (G4H * HID) / 4; C.lgK4[1] = 8;
    C.src[2] = (const float4*)w_ih2; C.dst[2] = (__half2*)(hp + O_WIH2); C.n4[2] = (G4H * HID) / 4; C.lgK4[2] = 8;
    C.src[3] = (const float4*)w_hh2; C.dst[3] = (__half2*)(hp + O_WHH2); C.n4[3] = (G4H * HID) / 4; C.lgK4[3] = 8;
    C.src[4] = (const float4*)w_ih3; C.dst[4] = (__half2*)(hp + O_WIH3); C.n4[4] = (G4H * HID) / 4; C.lgK4[4] = 8;
    C.src[5] = (const float4*)w_hh3; C.dst[5] = (__half2*)(hp + O_WHH3); C.n4[5] = (G4H * HID) / 4; C.lgK4[5] = 8;
    C.src[6] = (const float4*)h0;    C.dst[6] = (__half2*)(hp + O_H0);   C.n4[6] = (BATCH * HID) / 4; C.lgK4[6] = 0;
    C.src[7] = (const float4*)h1;    C.dst[7] = (__half2*)(hp + O_H1);   C.n4[7] = (BATCH * HID) / 4; C.lgK4[7] = 0;
    C.src[8] = (const float4*)h2;    C.dst[8] = (__half2*)(hp + O_H2);   C.n4[8] = (BATCH * HID) / 4; C.lgK4[8] = 0;
    k_cvt<<<CVT_GRID, 256>>>(C);

    // --- bias perms (one launch, 3 jobs) ---
    BiasJobs BJ;
    BJ.bih[0] = b_ih1; BJ.bhh[0] = b_hh1;
    BJ.bih[1] = b_ih2; BJ.bhh[1] = b_hh2;
    BJ.bih[2] = b_ih3; BJ.bhh[2] = b_hh3;
    k_bias_perm<<<(3 * G4H) / 256, 256>>>(BJ, biasp);

    // --- embedding GEMM (fp32, 64x64 tiles, reg double-buffered) ---
    emb_gemm_cvt<<<dim3(KPS / 64, BATCH / 64), 256>>>(kps, W_emb, b_emb, hp + O_X);

    // --- fused LSTM GEMMs (plain fp16, 64x64 warp tiles, frag dbuf) ---
    AllArgs A;
    {   // LSTM1: x@wih1^T + h0@whh1^T
        LstmArgs& L = A.l[0];
        L.seg[0] = { hp + O_X,  hp + O_WIH1, KPS, KPS, KPS };
        L.seg[1] = { hp + O_H0, hp + O_WHH1, HID, HID, HID };
        L.bias = biasp + 0 * G4H; L.c_old = c0;
        L.h_out = out_h0n; L.h_out2 = nullptr; L.c_out = out_c0n;
    }
    {   // LSTM2: h0@wih2^T + h1@whh2^T (old h0 per reference)
        LstmArgs& L = A.l[1];
        L.seg[0] = { hp + O_H0, hp + O_WIH2, HID, HID, HID };
        L.seg[1] = { hp + O_H1, hp + O_WHH2, HID, HID, HID };
        L.bias = biasp + 1 * G4H; L.c_old = c1;
        L.h_out = out_h1n; L.h_out2 = nullptr; L.c_out = out_c1n;
    }
    {   // LSTM3: h1@wih3^T + h2@whh3^T (old h1 per reference)
        LstmArgs& L = A.l[2];
        L.seg[0] = { hp + O_H1, hp + O_WIH3, HID, HID, HID };
        L.seg[1] = { hp + O_H2, hp + O_WHH3, HID, HID, HID };
        L.bias = biasp + 2 * G4H; L.c_old = c2;
        L.h_out = out_h2n_a; L.h_out2 = out_h2n_b; L.c_out = out_c2n;
    }

    cudaFuncSetAttribute(lstm_gemm, cudaFuncAttributeMaxDynamicSharedMemorySize, SMEM_SZ);
    lstm_gemm<<<dim3(G4H / BN, BATCH / BM, 3), 128, SMEM_SZ>>>(A);
}

// round 11
// speedup vs baseline: 1.0449x; 1.0449x over previous
#include <cuda_runtime.h>
#include <cuda_fp16.h>
#include <stdint.h>
#include <math.h>

#define HID   1024
#define BATCH 4096
#define KPS   256
#define G4H   4096

#define BM 128
#define BN 128
#define BK 64
#define NS 3
#define A_BYTES     (BM * BK * 2)          // 16 KB
#define STAGE_BYTES (2 * A_BYTES)          // 32 KB
#define SMEM_SZ     (NS * STAGE_BYTES)     // 96 KB

// ===========================================================================
// Scratch (__device__ globals; sanctioned no-alloc mechanism)
// ===========================================================================
#define MEL (1024 * 1024)
__device__ __align__(128) __half g_fp16[34 * MEL];   // 68 MB fp16 arena
__device__ float g_bias_perm[3 * G4H];

// arena offsets (half elements)
#define O_X     (0 * MEL)
#define O_H0    (1 * MEL)
#define O_H1    (5 * MEL)
#define O_H2    (9 * MEL)
#define O_WIH1  (13 * MEL)
#define O_WHH1  (14 * MEL)
#define O_WIH2  (18 * MEL)
#define O_WHH2  (22 * MEL)
#define O_WIH3  (26 * MEL)
#define O_WHH3  (30 * MEL)

// ===========================================================================
// Helpers
// ===========================================================================
__device__ __forceinline__ uint32_t smem_u32(const void* p) {
    uint32_t a;
    asm("{ .reg .u64 t; cvta.to.shared.u64 t, %1; cvt.u32.u64 %0, t; }" : "=r"(a) : "l"(p));
    return a;
}
__device__ __forceinline__ void cp_async16(uint32_t dst, const void* src) {
    asm volatile("cp.async.cg.shared.global [%0], [%1], 16;" :: "r"(dst), "l"(src));
}
__device__ __forceinline__ void ldsm_x4(uint32_t* r, uint32_t addr) {
    asm volatile("ldmatrix.sync.aligned.m8n8.x4.shared.b16 {%0,%1,%2,%3}, [%4];"
        : "=r"(r[0]), "=r"(r[1]), "=r"(r[2]), "=r"(r[3]) : "r"(addr));
}
__device__ __forceinline__ void mma16816(float* d, const uint32_t* a, uint32_t b0, uint32_t b1) {
    asm volatile("mma.sync.aligned.m16n8k16.row.col.f32.f16.f16.f32 "
        "{%0,%1,%2,%3}, {%4,%5,%6,%7}, {%8,%9}, {%0,%1,%2,%3};"
        : "+f"(d[0]), "+f"(d[1]), "+f"(d[2]), "+f"(d[3])
        : "r"(a[0]), "r"(a[1]), "r"(a[2]), "r"(a[3]), "r"(b0), "r"(b1));
}
__device__ __forceinline__ float sigmoidf_(float x) { return 1.0f / (1.0f + __expf(-x)); }

// ===========================================================================
// UNIFIED PREP KERNEL: one launch runs THREE independent jobs concurrently.
//   blocks [0, 256):        embedding fp32 SGEMM -> fp16 X
//   blocks [256, 1600):     9 fp32->fp16 converts (weights permuted, h plain)
//   blocks [1600, 1648):    bias permutes
// ===========================================================================
#define EMB_BLKS  256
#define CVT_BLKS  1344
#define BIAS_BLKS 48
#define PREP_GRID (EMB_BLKS + CVT_BLKS + BIAS_BLKS)
#define CJ0_BLK 64       // w_ih1 (smaller job)
#define CJB_BLK 160      // each 4M-element job

struct PrepArgs {
    // cvt jobs
    const float4* src[9];
    __half2* dst[9];
    int n4[9];
    int lgK4[9];           // 0 = plain; else log2(K/4) for gate-interleave permute
    // bias jobs
    const float* bih[3];
    const float* bhh[3];
    float* biasp;
    // emb gemm
    const float* embA;     // kps [4096,256]
    const float* embW;     // W_emb [256,256]
    const float* embBias;  // [256]
    __half* embC;          // X fp16 [4096,256]
};

__global__ void __launch_bounds__(256) k_prep(PrepArgs P) {
    const int bid = blockIdx.x;
    const int tid = threadIdx.x;

    if (bid < EMB_BLKS) {
        // ---------------- embedding SGEMM (64x64 tiles) ----------------
        const int K1 = KPS, N = KPS;
        __shared__ float As[16][64];
        __shared__ float Bs[16][64];
        const int m0 = (bid >> 2) * 64;
        const int n0 = (bid & 3) * 64;
        const int ty = tid >> 4, tx = tid & 15;
        float acc[4][4];
#pragma unroll
        for (int i = 0; i < 4; i++)
#pragma unroll
            for (int j = 0; j < 4; j++) acc[i][j] = 0.0f;

        const int lrow = tid >> 2, lcol4 = (tid & 3) * 4;
        float4 av = *(const float4*)(P.embA + (size_t)(m0 + lrow) * K1 + lcol4);
        float4 wv = *(const float4*)(P.embW + (size_t)(n0 + lrow) * K1 + lcol4);

        for (int k0 = 0; k0 < K1; k0 += 16) {
            As[lcol4 + 0][lrow] = av.x; As[lcol4 + 1][lrow] = av.y;
            As[lcol4 + 2][lrow] = av.z; As[lcol4 + 3][lrow] = av.w;
            Bs[lcol4 + 0][lrow] = wv.x; Bs[lcol4 + 1][lrow] = wv.y;
            Bs[lcol4 + 2][lrow] = wv.z; Bs[lcol4 + 3][lrow] = wv.w;
            __syncthreads();
            if (k0 + 16 < K1) {
                av = *(const float4*)(P.embA + (size_t)(m0 + lrow) * K1 + k0 + 16 + lcol4);
                wv = *(const float4*)(P.embW + (size_t)(n0 + lrow) * K1 + k0 + 16 + lcol4);
            }
#pragma unroll
            for (int k = 0; k < 16; k++) {
                float ar[4], br[4];
#pragma unroll
                for (int i = 0; i < 4; i++) ar[i] = As[k][ty * 4 + i];
#pragma unroll
                for (int j = 0; j < 4; j++) br[j] = Bs[k][tx * 4 + j];
#pragma unroll
                for (int i = 0; i < 4; i++)
#pragma unroll
                    for (int j = 0; j < 4; j++)
                        acc[i][j] = fmaf(ar[i], br[j], acc[i][j]);
            }
            __syncthreads();
        }
#pragma unroll
        for (int i = 0; i < 4; i++) {
            int m = m0 + ty * 4 + i;
            int n = n0 + tx * 4;
#pragma unroll
            for (int j = 0; j < 4; j++)
                P.embC[(size_t)m * N + n + j] = __float2half_rn(acc[i][j] + P.embBias[n + j]);
        }
    } else if (bid < EMB_BLKS + CVT_BLKS) {
        // ---------------- fp32 -> fp16 converts ----------------
        int cb = bid - EMB_BLKS;
        int job, lb, nb;
        if (cb < CJ0_BLK) { job = 0; lb = cb; nb = CJ0_BLK; }
        else { job = 1 + (cb - CJ0_BLK) / CJB_BLK; lb = (cb - CJ0_BLK) % CJB_BLK; nb = CJB_BLK; }
        const float4* __restrict__ src = P.src[job];
        __half2* __restrict__ dst = P.dst[job];
        const int n4 = P.n4[job];
        const int lg = P.lgK4[job];
        const int stride = nb * blockDim.x;
        if (lg == 0) {
            for (int i = lb * blockDim.x + tid; i < n4; i += stride) {
                float4 v = src[i];
                dst[2 * i + 0] = __floats2half2_rn(v.x, v.y);
                dst[2 * i + 1] = __floats2half2_rn(v.z, v.w);
            }
        } else {
            const int msk = (1 << lg) - 1;
            for (int i = lb * blockDim.x + tid; i < n4; i += stride) {
                int n = i >> lg, kc = i & msk;
                int g = n & 3, j = n >> 2;
                float4 v = src[(((size_t)g * HID + j) << lg) + kc];
                dst[2 * i + 0] = __floats2half2_rn(v.x, v.y);
                dst[2 * i + 1] = __floats2half2_rn(v.z, v.w);
            }
        }
    } else {
        // ---------------- bias permutes ----------------
        int idx = (bid - EMB_BLKS - CVT_BLKS) * 256 + tid;    // 0..3*4096
        int l = idx >> 12, n = idx & 4095;
        int g = n & 3, j = n >> 2;
        P.biasp[idx] = P.bih[l][g * HID + j] + P.bhh[l][g * HID + j];
    }
}

// ===========================================================================
// Fused LSTM GEMM (HMMA fp16): R7 schedule (load_stage at loop TAIL),
// CTA 128x128, 8 warps (4m x 2n), warp tile 32x64, 2 CTAs/SM.
// Weights pre-permuted -> linear B loads. 2 K-segments.
// ===========================================================================
struct SegInfo { const __half *A, *B; int K, ldA, ldB; };
struct LstmArgs {
    SegInfo seg[2];
    const float* bias;     // gate-interleaved [4096]: 4j+g
    const float* c_old;
    float* h_out; float* h_out2; float* c_out;
};
struct AllArgs { LstmArgs l[3]; };

__global__ void __launch_bounds__(256, 2) lstm_gemm(AllArgs args)
{
    extern __shared__ __align__(1024) char smem[];
    const LstmArgs& L = args.l[blockIdx.z];
    const int m0   = blockIdx.y * BM;
    const int n0   = blockIdx.x * BN;      // permuted-weight row base
    const int jb32 = n0 >> 2;
    const int tid  = threadIdx.x;
    const int lane = tid & 31, wid = tid >> 5;
    const int warp_m = wid & 3, warp_n = wid >> 2;   // 4 x 2
    const int wm0 = warp_m * 32, wn0 = warp_n * 64;
    const uint32_t sb = smem_u32(smem);

    const int k1 = L.seg[0].K >> 6;
    const int KT = k1 + (L.seg[1].K >> 6);

    float acc[16][4];
#pragma unroll
    for (int i = 0; i < 16; i++)
#pragma unroll
        for (int j = 0; j < 4; j++) acc[i][j] = 0.0f;

    auto load_stage = [&](int t) {
        const int s = t % NS;
        const int seg = (t >= k1) ? 1 : 0;
        const int k0 = (t - (seg ? k1 : 0)) << 6;
        const __half* Ap = L.seg[seg].A; const int ldA = L.seg[seg].ldA;
        const __half* Bp = L.seg[seg].B; const int ldB = L.seg[seg].ldB;
        const uint32_t sa = sb + s * STAGE_BYTES;
        const uint32_t sB = sa + A_BYTES;
#pragma unroll
        for (int i = 0; i < 4; i++) {
            int lin = tid + (i << 8);
            int r = lin >> 3, kc = lin & 7;
            cp_async16(sa + r * 128 + ((kc ^ (r & 7)) << 4),
                       Ap + (size_t)(m0 + r) * ldA + k0 + (kc << 3));
        }
#pragma unroll
        for (int i = 0; i < 4; i++) {
            int lin = tid + (i << 8);
            int n = lin >> 3, kc = lin & 7;
            cp_async16(sB + n * 128 + ((kc ^ (n & 7)) << 4),
                       Bp + (size_t)(n0 + n) * ldB + k0 + (kc << 3));
        }
        asm volatile("cp.async.commit_group;" ::: "memory");
    };

    // prologue: NS-1 stages ahead
    for (int s = 0; s < NS - 1; s++) load_stage(s);

    for (int t = 0; t < KT; t++) {
        asm volatile("cp.async.wait_group %0;" :: "n"(NS - 2) : "memory");
        __syncthreads();
        const uint32_t sa = sb + (t % NS) * STAGE_BYTES;
        const uint32_t sB = sa + A_BYTES;
#pragma unroll
        for (int kk = 0; kk < 4; kk++) {
            uint32_t afr[2][4];
#pragma unroll
            for (int mt = 0; mt < 2; mt++) {
                int row = wm0 + mt * 16 + (lane & 15);
                int kc = kk * 2 + (lane >> 4);
                ldsm_x4(afr[mt], sa + row * 128 + ((kc ^ (row & 7)) << 4));
            }
#pragma unroll
            for (int op = 0; op < 4; op++) {
                uint32_t bfr[4];
                int n = wn0 + op * 16 + ((lane >> 4) << 3) + (lane & 7);
                int kc = kk * 2 + ((lane >> 3) & 1);
                ldsm_x4(bfr, sB + n * 128 + ((kc ^ (n & 7)) << 4));
#pragma unroll
                for (int mt = 0; mt < 2; mt++) {
                    mma16816(acc[mt * 8 + op * 2 + 0], afr[mt], bfr[0], bfr[1]);
                    mma16816(acc[mt * 8 + op * 2 + 1], afr[mt], bfr[2], bfr[3]);
                }
            }
        }
        if (t + NS - 1 < KT) load_stage(t + NS - 1);   // R7 tail placement
    }

    // --------------------------------------------------------------
    // Fused LSTM epilogue (gate-interleaved cols; shfl pairs (i,f)/(g,o)).
    // --------------------------------------------------------------
    const float* __restrict__ bias = L.bias;
    const float* __restrict__ cold = L.c_old;
    const int qid = lane & 3;
#pragma unroll
    for (int mt = 0; mt < 2; mt++) {
#pragma unroll
        for (int oct = 0; oct < 8; oct++) {
            float c0 = acc[mt * 8 + oct][0], c1 = acc[mt * 8 + oct][1];
            float c2 = acc[mt * 8 + oct][2], c3 = acc[mt * 8 + oct][3];
            float o0 = __shfl_xor_sync(0xffffffffu, c0, 1);
            float o1 = __shfl_xor_sync(0xffffffffu, c1, 1);
            float o2 = __shfl_xor_sync(0xffffffffu, c2, 1);
            float o3 = __shfl_xor_sync(0xffffffffu, c3, 1);
            float gi, gf, gg, go;
            int r;
            if ((lane & 1) == 0) {      // even lane: owns (i,f), receives (g,o); row+8
                gi = c2; gf = c3; gg = o2; go = o3;
                r = wm0 + mt * 16 + (lane >> 2) + 8;
            } else {                    // odd lane: owns (g,o), receives (i,f); row
                gi = o0; gf = o1; gg = c0; go = c1;
                r = wm0 + mt * 16 + (lane >> 2);
            }
            const int j = jb32 + warp_n * 16 + oct * 2 + (qid >> 1);
            const float4 bb = *(const float4*)(bias + 4 * j);
            gi = sigmoidf_(gi + bb.x);
            gf = sigmoidf_(gf + bb.y);
            gg = tanhf(gg + bb.z);
            go = sigmoidf_(go + bb.w);
            const size_t idx = (size_t)(m0 + r) * HID + j;
            float cn = gf * cold[idx] + gi * gg;
            float hn = go * tanhf(cn);
            L.c_out[idx] = cn;
            L.h_out[idx] = hn;
            if (L.h_out2) L.h_out2[idx] = hn;
        }
    }
}

// ===========================================================================
extern "C" void kernel_launch(void* const* d_in, const int* in_sizes, int n_in,
                              void* d_out, int out_size)
{
    const float* kps   = (const float*)d_in[0];
    const float* h0    = (const float*)d_in[1];
    const float* h1    = (const float*)d_in[2];
    const float* h2    = (const float*)d_in[3];
    const float* c0    = (const float*)d_in[4];
    const float* c1    = (const float*)d_in[5];
    const float* c2    = (const float*)d_in[6];
    const float* W_emb = (const float*)d_in[7];
    const float* b_emb = (const float*)d_in[8];
    const float* w_ih1 = (const float*)d_in[9];
    const float* w_hh1 = (const float*)d_in[10];
    const float* b_ih1 = (const float*)d_in[11];
    const float* b_hh1 = (const float*)d_in[12];
    const float* w_ih2 = (const float*)d_in[13];
    const float* w_hh2 = (const float*)d_in[14];
    const float* b_ih2 = (const float*)d_in[15];
    const float* b_hh2 = (const float*)d_in[16];
    const float* w_ih3 = (const float*)d_in[17];
    const float* w_hh3 = (const float*)d_in[18];
    const float* b_ih3 = (const float*)d_in[19];
    const float* b_hh3 = (const float*)d_in[20];

    float* out = (float*)d_out;
    const size_t S = (size_t)BATCH * HID;
    float* out_h2n_a = out + 0 * S;
    float* out_h0n   = out + 1 * S;
    float* out_h1n   = out + 2 * S;
    float* out_h2n_b = out + 3 * S;
    float* out_c0n   = out + 4 * S;
    float* out_c1n   = out + 5 * S;
    float* out_c2n   = out + 6 * S;

    __half* hp = nullptr;
    float* biasp = nullptr;
    cudaGetSymbolAddress((void**)&hp, g_fp16);
    cudaGetSymbolAddress((void**)&biasp, g_bias_perm);

    // --- ONE prep launch: converts + bias perms + embedding GEMM ---
    PrepArgs P;
    P.src[0] = (const float4*)w_ih1; P.dst[0] = (__half2*)(hp + O_WIH1); P.n4[0] = (G4H * KPS) / 4; P.lgK4[0] = 6;
    P.src[1] = (const float4*)w_hh1; P.dst[1] = (__half2*)(hp + O_WHH1); P.n4[1] = (G4H * HID) / 4; P.lgK4[1] = 8;
    P.src[2] = (const float4*)w_ih2; P.dst[2] = (__half2*)(hp + O_WIH2); P.n4[2] = (G4H * HID) / 4; P.lgK4[2] = 8;
    P.src[3] = (const float4*)w_hh2; P.dst[3] = (__half2*)(hp + O_WHH2); P.n4[3] = (G4H * HID) / 4; P.lgK4[3] = 8;
    P.src[4] = (const float4*)w_ih3; P.dst[4] = (__half2*)(hp + O_WIH3); P.n4[4] = (G4H * HID) / 4; P.lgK4[4] = 8;
    P.src[5] = (const float4*)w_hh3; P.dst[5] = (__half2*)(hp + O_WHH3); P.n4[5] = (G4H * HID) / 4; P.lgK4[5] = 8;
    P.src[6] = (const float4*)h0;    P.dst[6] = (__half2*)(hp + O_H0);   P.n4[6] = (BATCH * HID) / 4; P.lgK4[6] = 0;
    P.src[7] = (const float4*)h1;    P.dst[7] = (__half2*)(hp + O_H1);   P.n4[7] = (BATCH * HID) / 4; P.lgK4[7] = 0;
    P.src[8] = (const float4*)h2;    P.dst[8] = (__half2*)(hp + O_H2);   P.n4[8] = (BATCH * HID) / 4; P.lgK4[8] = 0;
    P.bih[0] = b_ih1; P.bhh[0] = b_hh1;
    P.bih[1] = b_ih2; P.bhh[1] = b_hh2;
    P.bih[2] = b_ih3; P.bhh[2] = b_hh3;
    P.biasp = biasp;
    P.embA = kps; P.embW = W_emb; P.embBias = b_emb; P.embC = hp + O_X;
    k_prep<<<PREP_GRID, 256>>>(P);

    // --- fused LSTM GEMMs (plain fp16, R7 schedule) ---
    AllArgs A;
    {   // LSTM1: x@wih1^T + h0@whh1^T
        LstmArgs& L = A.l[0];
        L.seg[0] = { hp + O_X,  hp + O_WIH1, KPS, KPS, KPS };
        L.seg[1] = { hp + O_H0, hp + O_WHH1, HID, HID, HID };
        L.bias = biasp + 0 * G4H; L.c_old = c0;
        L.h_out = out_h0n; L.h_out2 = nullptr; L.c_out = out_c0n;
    }
    {   // LSTM2: h0@wih2^T + h1@whh2^T (old h0 per reference)
        LstmArgs& L = A.l[1];
        L.seg[0] = { hp + O_H0, hp + O_WIH2, HID, HID, HID };
        L.seg[1] = { hp + O_H1, hp + O_WHH2, HID, HID, HID };
        L.bias = biasp + 1 * G4H; L.c_old = c1;
        L.h_out = out_h1n; L.h_out2 = nullptr; L.c_out = out_c1n;
    }
    {   // LSTM3: h1@wih3^T + h2@whh3^T (old h1 per reference)
        LstmArgs& L = A.l[2];
        L.seg[0] = { hp + O_H1, hp + O_WIH3, HID, HID, HID };
        L.seg[1] = { hp + O_H2, hp + O_WHH3, HID, HID, HID };
        L.bias = biasp + 2 * G4H; L.c_old = c2;
        L.h_out = out_h2n_a; L.h_out2 = out_h2n_b; L.c_out = out_c2n;
    }

    cudaFuncSetAttribute(lstm_gemm, cudaFuncAttributeMaxDynamicSharedMemorySize, SMEM_SZ);
    lstm_gemm<<<dim3(G4H / BN, BATCH / BM, 3), 256, SMEM_SZ>>>(A);
}

// round 14
// speedup vs baseline: 1.0450x; 1.0001x over previous
#include <cuda_runtime.h>
#include <cuda_fp16.h>
#include <stdint.h>
#include <math.h>

#define HID   1024
#define BATCH 4096
#define KPS   256
#define G4H   4096

#define BM 128
#define BN 128
#define BK 64
#define NS 3
#define A_BYTES     (BM * BK * 2)          // 16 KB
#define STAGE_BYTES (2 * A_BYTES)          // 32 KB
#define SMEM_SZ     (NS * STAGE_BYTES)     // 96 KB

// ===========================================================================
// Scratch (__device__ globals; sanctioned no-alloc mechanism)
// ===========================================================================
#define MEL (1024 * 1024)
__device__ __align__(128) __half g_fp16[34 * MEL];   // 68 MB fp16 arena
__device__ float g_bias_perm[3 * G4H];

// arena offsets (half elements)
#define O_X     (0 * MEL)
#define O_H0    (1 * MEL)
#define O_H1    (5 * MEL)
#define O_H2    (9 * MEL)
#define O_WIH1  (13 * MEL)
#define O_WHH1  (14 * MEL)
#define O_WIH2  (18 * MEL)
#define O_WHH2  (22 * MEL)
#define O_WIH3  (26 * MEL)
#define O_WHH3  (30 * MEL)

// ===========================================================================
// Helpers
// ===========================================================================
__device__ __forceinline__ uint32_t smem_u32(const void* p) {
    uint32_t a;
    asm("{ .reg .u64 t; cvta.to.shared.u64 t, %1; cvt.u32.u64 %0, t; }" : "=r"(a) : "l"(p));
    return a;
}
__device__ __forceinline__ void cp_async16(uint32_t dst, const void* src) {
    asm volatile("cp.async.cg.shared.global [%0], [%1], 16;" :: "r"(dst), "l"(src));
}
__device__ __forceinline__ void ldsm_x4(uint32_t* r, uint32_t addr) {
    asm volatile("ldmatrix.sync.aligned.m8n8.x4.shared.b16 {%0,%1,%2,%3}, [%4];"
        : "=r"(r[0]), "=r"(r[1]), "=r"(r[2]), "=r"(r[3]) : "r"(addr));
}
__device__ __forceinline__ void mma16816(float* d, const uint32_t* a, uint32_t b0, uint32_t b1) {
    asm volatile("mma.sync.aligned.m16n8k16.row.col.f32.f16.f16.f32 "
        "{%0,%1,%2,%3}, {%4,%5,%6,%7}, {%8,%9}, {%0,%1,%2,%3};"
        : "+f"(d[0]), "+f"(d[1]), "+f"(d[2]), "+f"(d[3])
        : "r"(a[0]), "r"(a[1]), "r"(a[2]), "r"(a[3]), "r"(b0), "r"(b1));
}
// fast activations (exonerated by R13: corruption persisted with exact forms)
__device__ __forceinline__ float fast_sigmoid(float x) {
    return __fdividef(1.0f, 1.0f + __expf(-x));
}
__device__ __forceinline__ float fast_tanh(float x) {
    return 1.0f - __fdividef(2.0f, __expf(2.0f * x) + 1.0f);
}

// ===========================================================================
// UNIFIED PREP KERNEL (R11): one launch runs THREE independent jobs.
//   blocks [0, 256):        embedding fp32 SGEMM -> fp16 X
//   blocks [256, 1600):     9 fp32->fp16 converts (weights permuted, h plain)
//   blocks [1600, 1648):    bias permutes
// ===========================================================================
#define EMB_BLKS  256
#define CVT_BLKS  1344
#define BIAS_BLKS 48
#define PREP_GRID (EMB_BLKS + CVT_BLKS + BIAS_BLKS)
#define CJ0_BLK 64
#define CJB_BLK 160

struct PrepArgs {
    const float4* src[9];
    __half2* dst[9];
    int n4[9];
    int lgK4[9];           // 0 = plain; else log2(K/4) for gate-interleave permute
    const float* bih[3];
    const float* bhh[3];
    float* biasp;
    const float* embA;
    const float* embW;
    const float* embBias;
    __half* embC;
};

__global__ void __launch_bounds__(256) k_prep(PrepArgs P) {
    const int bid = blockIdx.x;
    const int tid = threadIdx.x;

    if (bid < EMB_BLKS) {
        const int K1 = KPS, N = KPS;
        __shared__ float As[16][64];
        __shared__ float Bs[16][64];
        const int m0 = (bid >> 2) * 64;
        const int n0 = (bid & 3) * 64;
        const int ty = tid >> 4, tx = tid & 15;
        float acc[4][4];
#pragma unroll
        for (int i = 0; i < 4; i++)
#pragma unroll
            for (int j = 0; j < 4; j++) acc[i][j] = 0.0f;

        const int lrow = tid >> 2, lcol4 = (tid & 3) * 4;
        float4 av = *(const float4*)(P.embA + (size_t)(m0 + lrow) * K1 + lcol4);
        float4 wv = *(const float4*)(P.embW + (size_t)(n0 + lrow) * K1 + lcol4);

        for (int k0 = 0; k0 < K1; k0 += 16) {
            As[lcol4 + 0][lrow] = av.x; As[lcol4 + 1][lrow] = av.y;
            As[lcol4 + 2][lrow] = av.z; As[lcol4 + 3][lrow] = av.w;
            Bs[lcol4 + 0][lrow] = wv.x; Bs[lcol4 + 1][lrow] = wv.y;
            Bs[lcol4 + 2][lrow] = wv.z; Bs[lcol4 + 3][lrow] = wv.w;
            __syncthreads();
            if (k0 + 16 < K1) {
                av = *(const float4*)(P.embA + (size_t)(m0 + lrow) * K1 + k0 + 16 + lcol4);
                wv = *(const float4*)(P.embW + (size_t)(n0 + lrow) * K1 + k0 + 16 + lcol4);
            }
#pragma unroll
            for (int k = 0; k < 16; k++) {
                float ar[4], br[4];
#pragma unroll
                for (int i = 0; i < 4; i++) ar[i] = As[k][ty * 4 + i];
#pragma unroll
                for (int j = 0; j < 4; j++) br[j] = Bs[k][tx * 4 + j];
#pragma unroll
                for (int i = 0; i < 4; i++)
#pragma unroll
                    for (int j = 0; j < 4; j++)
                        acc[i][j] = fmaf(ar[i], br[j], acc[i][j]);
            }
            __syncthreads();
        }
#pragma unroll
        for (int i = 0; i < 4; i++) {
            int m = m0 + ty * 4 + i;
            int n = n0 + tx * 4;
#pragma unroll
            for (int j = 0; j < 4; j++)
                P.embC[(size_t)m * N + n + j] = __float2half_rn(acc[i][j] + P.embBias[n + j]);
        }
    } else if (bid < EMB_BLKS + CVT_BLKS) {
        int cb = bid - EMB_BLKS;
        int job, lb, nb;
        if (cb < CJ0_BLK) { job = 0; lb = cb; nb = CJ0_BLK; }
        else { job = 1 + (cb - CJ0_BLK) / CJB_BLK; lb = (cb - CJ0_BLK) % CJB_BLK; nb = CJB_BLK; }
        const float4* __restrict__ src = P.src[job];
        __half2* __restrict__ dst = P.dst[job];
        const int n4 = P.n4[job];
        const int lg = P.lgK4[job];
        const int stride = nb * blockDim.x;
        if (lg == 0) {
            for (int i = lb * blockDim.x + tid; i < n4; i += stride) {
                float4 v = src[i];
                dst[2 * i + 0] = __floats2half2_rn(v.x, v.y);
                dst[2 * i + 1] = __floats2half2_rn(v.z, v.w);
            }
        } else {
            const int msk = (1 << lg) - 1;
            for (int i = lb * blockDim.x + tid; i < n4; i += stride) {
                int n = i >> lg, kc = i & msk;
                int g = n & 3, j = n >> 2;
                float4 v = src[(((size_t)g * HID + j) << lg) + kc];
                dst[2 * i + 0] = __floats2half2_rn(v.x, v.y);
                dst[2 * i + 1] = __floats2half2_rn(v.z, v.w);
            }
        }
    } else {
        int idx = (bid - EMB_BLKS - CVT_BLKS) * 256 + tid;
        int l = idx >> 12, n = idx & 4095;
        int g = n & 3, j = n >> 2;
        P.biasp[idx] = P.bih[l][g * HID + j] + P.bhh[l][g * HID + j];
    }
}

// ===========================================================================
// Fused LSTM GEMM (HMMA fp16): R7/R11 schedule (load_stage at loop TAIL),
// CTA 128x128, 8 warps (4m x 2n), warp tile 32x64, 2 CTAs/SM.
// Weights pre-permuted -> linear B loads. 2 K-segments.
// Epilogue: fast activations (only change vs R11).
// ===========================================================================
struct SegInfo { const __half *A, *B; int K, ldA, ldB; };
struct LstmArgs {
    SegInfo seg[2];
    const float* bias;     // gate-interleaved [4096]: 4j+g
    const float* c_old;
    float* h_out; float* h_out2; float* c_out;
};
struct AllArgs { LstmArgs l[3]; };

__global__ void __launch_bounds__(256, 2) lstm_gemm(AllArgs args)
{
    extern __shared__ __align__(1024) char smem[];
    const LstmArgs& L = args.l[blockIdx.z];
    const int m0   = blockIdx.y * BM;
    const int n0   = blockIdx.x * BN;      // permuted-weight row base
    const int jb32 = n0 >> 2;
    const int tid  = threadIdx.x;
    const int lane = tid & 31, wid = tid >> 5;
    const int warp_m = wid & 3, warp_n = wid >> 2;   // 4 x 2
    const int wm0 = warp_m * 32, wn0 = warp_n * 64;
    const uint32_t sb = smem_u32(smem);

    const int k1 = L.seg[0].K >> 6;
    const int KT = k1 + (L.seg[1].K >> 6);

    float acc[16][4];
#pragma unroll
    for (int i = 0; i < 16; i++)
#pragma unroll
        for (int j = 0; j < 4; j++) acc[i][j] = 0.0f;

    auto load_stage = [&](int t) {
        const int s = t % NS;
        const int seg = (t >= k1) ? 1 : 0;
        const int k0 = (t - (seg ? k1 : 0)) << 6;
        const __half* Ap = L.seg[seg].A; const int ldA = L.seg[seg].ldA;
        const __half* Bp = L.seg[seg].B; const int ldB = L.seg[seg].ldB;
        const uint32_t sa = sb + s * STAGE_BYTES;
        const uint32_t sB = sa + A_BYTES;
#pragma unroll
        for (int i = 0; i < 4; i++) {
            int lin = tid + (i << 8);
            int r = lin >> 3, kc = lin & 7;
            cp_async16(sa + r * 128 + ((kc ^ (r & 7)) << 4),
                       Ap + (size_t)(m0 + r) * ldA + k0 + (kc << 3));
        }
#pragma unroll
        for (int i = 0; i < 4; i++) {
            int lin = tid + (i << 8);
            int n = lin >> 3, kc = lin & 7;
            cp_async16(sB + n * 128 + ((kc ^ (n & 7)) << 4),
                       Bp + (size_t)(n0 + n) * ldB + k0 + (kc << 3));
        }
        asm volatile("cp.async.commit_group;" ::: "memory");
    };

    for (int s = 0; s < NS - 1; s++) load_stage(s);

    for (int t = 0; t < KT; t++) {
        asm volatile("cp.async.wait_group %0;" :: "n"(NS - 2) : "memory");
        __syncthreads();
        const uint32_t sa = sb + (t % NS) * STAGE_BYTES;
        const uint32_t sB = sa + A_BYTES;
#pragma unroll
        for (int kk = 0; kk < 4; kk++) {
            uint32_t afr[2][4];
#pragma unroll
            for (int mt = 0; mt < 2; mt++) {
                int row = wm0 + mt * 16 + (lane & 15);
                int kc = kk * 2 + (lane >> 4);
                ldsm_x4(afr[mt], sa + row * 128 + ((kc ^ (row & 7)) << 4));
            }
#pragma unroll
            for (int op = 0; op < 4; op++) {
                uint32_t bfr[4];
                int n = wn0 + op * 16 + ((lane >> 4) << 3) + (lane & 7);
                int kc = kk * 2 + ((lane >> 3) & 1);
                ldsm_x4(bfr, sB + n * 128 + ((kc ^ (n & 7)) << 4));
#pragma unroll
                for (int mt = 0; mt < 2; mt++) {
                    mma16816(acc[mt * 8 + op * 2 + 0], afr[mt], bfr[0], bfr[1]);
                    mma16816(acc[mt * 8 + op * 2 + 1], afr[mt], bfr[2], bfr[3]);
                }
            }
        }
        if (t + NS - 1 < KT) load_stage(t + NS - 1);   // tail placement
    }

    // ---- fused LSTM epilogue (fast activations) ----
    const float* __restrict__ bias = L.bias;
    const float* __restrict__ cold = L.c_old;
    const int qid = lane & 3;
#pragma unroll
    for (int mt = 0; mt < 2; mt++) {
#pragma unroll
        for (int oct = 0; oct < 8; oct++) {
            float c0 = acc[mt * 8 + oct][0], c1 = acc[mt * 8 + oct][1];
            float c2 = acc[mt * 8 + oct][2], c3 = acc[mt * 8 + oct][3];
            float o0 = __shfl_xor_sync(0xffffffffu, c0, 1);
            float o1 = __shfl_xor_sync(0xffffffffu, c1, 1);
            float o2 = __shfl_xor_sync(0xffffffffu, c2, 1);
            float o3 = __shfl_xor_sync(0xffffffffu, c3, 1);
            float gi, gf, gg, go;
            int r;
            if ((lane & 1) == 0) {      // even lane: owns (i,f), receives (g,o); row+8
                gi = c2; gf = c3; gg = o2; go = o3;
                r = wm0 + mt * 16 + (lane >> 2) + 8;
            } else {                    // odd lane: owns (g,o), receives (i,f); row
                gi = o0; gf = o1; gg = c0; go = c1;
                r = wm0 + mt * 16 + (lane >> 2);
            }
            const int j = jb32 + warp_n * 16 + oct * 2 + (qid >> 1);
            const float4 bb = *(const float4*)(bias + 4 * j);
            gi = fast_sigmoid(gi + bb.x);
            gf = fast_sigmoid(gf + bb.y);
            gg = fast_tanh(gg + bb.z);
            go = fast_sigmoid(go + bb.w);
            const size_t idx = (size_t)(m0 + r) * HID + j;
            float cn = gf * cold[idx] + gi * gg;
            float hn = go * fast_tanh(cn);
            L.c_out[idx] = cn;
            L.h_out[idx] = hn;
            if (L.h_out2) L.h_out2[idx] = hn;
        }
    }
}

// ===========================================================================
extern "C" void kernel_launch(void* const* d_in, const int* in_sizes, int n_in,
                              void* d_out, int out_size)
{
    const float* kps   = (const float*)d_in[0];
    const float* h0    = (const float*)d_in[1];
    const float* h1    = (const float*)d_in[2];
    const float* h2    = (const float*)d_in[3];
    const float* c0    = (const float*)d_in[4];
    const float* c1    = (const float*)d_in[5];
    const float* c2    = (const float*)d_in[6];
    const float* W_emb = (const float*)d_in[7];
    const float* b_emb = (const float*)d_in[8];
    const float* w_ih1 = (const float*)d_in[9];
    const float* w_hh1 = (const float*)d_in[10];
    const float* b_ih1 = (const float*)d_in[11];
    const float* b_hh1 = (const float*)d_in[12];
    const float* w_ih2 = (const float*)d_in[13];
    const float* w_hh2 = (const float*)d_in[14];
    const float* b_ih2 = (const float*)d_in[15];
    const float* b_hh2 = (const float*)d_in[16];
    const float* w_ih3 = (const float*)d_in[17];
    const float* w_hh3 = (const float*)d_in[18];
    const float* b_ih3 = (const float*)d_in[19];
    const float* b_hh3 = (const float*)d_in[20];

    float* out = (float*)d_out;
    const size_t S = (size_t)BATCH * HID;
    float* out_h2n_a = out + 0 * S;
    float* out_h0n   = out + 1 * S;
    float* out_h1n   = out + 2 * S;
    float* out_h2n_b = out + 3 * S;
    float* out_c0n   = out + 4 * S;
    float* out_c1n   = out + 5 * S;
    float* out_c2n   = out + 6 * S;

    __half* hp = nullptr;
    float* biasp = nullptr;
    cudaGetSymbolAddress((void**)&hp, g_fp16);
    cudaGetSymbolAddress((void**)&biasp, g_bias_perm);

    // --- ONE prep launch: converts + bias perms + embedding GEMM ---
    PrepArgs P;
    P.src[0] = (const float4*)w_ih1; P.dst[0] = (__half2*)(hp + O_WIH1); P.n4[0] = (G4H * KPS) / 4; P.lgK4[0] = 6;
    P.src[1] = (const float4*)w_hh1; P.dst[1] = (__half2*)(hp + O_WHH1); P.n4[1] = (G4H * HID) / 4; P.lgK4[1] = 8;
    P.src[2] = (const float4*)w_ih2; P.dst[2] = (__half2*)(hp + O_WIH2); P.n4[2] = (G4H * HID) / 4; P.lgK4[2] = 8;
    P.src[3] = (const float4*)w_hh2; P.dst[3] = (__half2*)(hp + O_WHH2); P.n4[3] = (G4H * HID) / 4; P.lgK4[3] = 8;
    P.src[4] = (const float4*)w_ih3; P.dst[4] = (__half2*)(hp + O_WIH3); P.n4[4] = (G4H * HID) / 4; P.lgK4[4] = 8;
    P.src[5] = (const float4*)w_hh3; P.dst[5] = (__half2*)(hp + O_WHH3); P.n4[5] = (G4H * HID) / 4; P.lgK4[5] = 8;
    P.src[6] = (const float4*)h0;    P.dst[6] = (__half2*)(hp + O_H0);   P.n4[6] = (BATCH * HID) / 4; P.lgK4[6] = 0;
    P.src[7] = (const float4*)h1;    P.dst[7] = (__half2*)(hp + O_H1);   P.n4[7] = (BATCH * HID) / 4; P.lgK4[7] = 0;
    P.src[8] = (const float4*)h2;    P.dst[8] = (__half2*)(hp + O_H2);   P.n4[8] = (BATCH * HID) / 4; P.lgK4[8] = 0;
    P.bih[0] = b_ih1; P.bhh[0] = b_hh1;
    P.bih[1] = b_ih2; P.bhh[1] = b_hh2;
    P.bih[2] = b_ih3; P.bhh[2] = b_hh3;
    P.biasp = biasp;
    P.embA = kps; P.embW = W_emb; P.embBias = b_emb; P.embC = hp + O_X;
    k_prep<<<PREP_GRID, 256>>>(P);

    // --- fused LSTM GEMMs (plain fp16, R11 schedule) ---
    AllArgs A;
    {   // LSTM1: x@wih1^T + h0@whh1^T
        LstmArgs& L = A.l[0];
        L.seg[0] = { hp + O_X,  hp + O_WIH1, KPS, KPS, KPS };
        L.seg[1] = { hp + O_H0, hp + O_WHH1, HID, HID, HID };
        L.bias = biasp + 0 * G4H; L.c_old = c0;
        L.h_out = out_h0n; L.h_out2 = nullptr; L.c_out = out_c0n;
    }
    {   // LSTM2: h0@wih2^T + h1@whh2^T (old h0 per reference)
        LstmArgs& L = A.l[1];
        L.seg[0] = { hp + O_H0, hp + O_WIH2, HID, HID, HID };
        L.seg[1] = { hp + O_H1, hp + O_WHH2, HID, HID, HID };
        L.bias = biasp + 1 * G4H; L.c_old = c1;
        L.h_out = out_h1n; L.h_out2 = nullptr; L.c_out = out_c1n;
    }
    {   // LSTM3: h1@wih3^T + h2@whh3^T (old h1 per reference)
        LstmArgs& L = A.l[2];
        L.seg[0] = { hp + O_H1, hp + O_WIH3, HID, HID, HID };
        L.seg[1] = { hp + O_H2, hp + O_WHH3, HID, HID, HID };
        L.bias = biasp + 2 * G4H; L.c_old = c2;
        L.h_out = out_h2n_a; L.h_out2 = out_h2n_b; L.c_out = out_c2n;
    }

    cudaFuncSetAttribute(lstm_gemm, cudaFuncAttributeMaxDynamicSharedMemorySize, SMEM_SZ);
    lstm_gemm<<<dim3(G4H / BN, BATCH / BM, 3), 256, SMEM_SZ>>>(A);
}

// round 16
// speedup vs baseline: 1.1129x; 1.0650x over previous
#include <cuda_runtime.h>
#include <cuda_fp16.h>
#include <stdint.h>
#include <math.h>

#define HID   1024
#define BATCH 4096
#define KPS   256
#define G4H   4096

#define BM 128
#define BN 128
#define BK 64
#define NS 2
#define A_BYTES     (BM * BK * 2)          // 16 KB
#define STAGE_BYTES (2 * A_BYTES)          // 32 KB
#define SMEM_SZ     (NS * STAGE_BYTES)     // 64 KB

// ===========================================================================
// Scratch (__device__ globals; sanctioned no-alloc mechanism)
// ===========================================================================
#define MEL (1024 * 1024)
__device__ __align__(128) __half g_fp16[34 * MEL];   // 68 MB fp16 arena
__device__ float g_bias_perm[3 * G4H];

// arena offsets (half elements)
#define O_X     (0 * MEL)
#define O_H0    (1 * MEL)
#define O_H1    (5 * MEL)
#define O_H2    (9 * MEL)
#define O_WIH1  (13 * MEL)
#define O_WHH1  (14 * MEL)
#define O_WIH2  (18 * MEL)
#define O_WHH2  (22 * MEL)
#define O_WIH3  (26 * MEL)
#define O_WHH3  (30 * MEL)

// ===========================================================================
// Helpers
// ===========================================================================
__device__ __forceinline__ uint32_t smem_u32(const void* p) {
    uint32_t a;
    asm("{ .reg .u64 t; cvta.to.shared.u64 t, %1; cvt.u32.u64 %0, t; }" : "=r"(a) : "l"(p));
    return a;
}
__device__ __forceinline__ void cp_async16(uint32_t dst, const void* src) {
    asm volatile("cp.async.cg.shared.global [%0], [%1], 16;" :: "r"(dst), "l"(src));
}
__device__ __forceinline__ void ldsm_x4(uint32_t* r, uint32_t addr) {
    asm volatile("ldmatrix.sync.aligned.m8n8.x4.shared.b16 {%0,%1,%2,%3}, [%4];"
        : "=r"(r[0]), "=r"(r[1]), "=r"(r[2]), "=r"(r[3]) : "r"(addr));
}
__device__ __forceinline__ void mma16816(float* d, const uint32_t* a, uint32_t b0, uint32_t b1) {
    asm volatile("mma.sync.aligned.m16n8k16.row.col.f32.f16.f16.f32 "
        "{%0,%1,%2,%3}, {%4,%5,%6,%7}, {%8,%9}, {%0,%1,%2,%3};"
        : "+f"(d[0]), "+f"(d[1]), "+f"(d[2]), "+f"(d[3])
        : "r"(a[0]), "r"(a[1]), "r"(a[2]), "r"(a[3]), "r"(b0), "r"(b1));
}
__device__ __forceinline__ float fast_sigmoid(float x) {
    return __fdividef(1.0f, 1.0f + __expf(-x));
}
__device__ __forceinline__ float fast_tanh(float x) {
    return 1.0f - __fdividef(2.0f, __expf(2.0f * x) + 1.0f);
}

// ===========================================================================
// UNIFIED PREP KERNEL (R14, unchanged — proven deterministic)
// ===========================================================================
#define EMB_BLKS  256
#define CVT_BLKS  1344
#define BIAS_BLKS 48
#define PREP_GRID (EMB_BLKS + CVT_BLKS + BIAS_BLKS)
#define CJ0_BLK 64
#define CJB_BLK 160

struct PrepArgs {
    const float4* src[9];
    __half2* dst[9];
    int n4[9];
    int lgK4[9];
    const float* bih[3];
    const float* bhh[3];
    float* biasp;
    const float* embA;
    const float* embW;
    const float* embBias;
    __half* embC;
};

__global__ void __launch_bounds__(256) k_prep(PrepArgs P) {
    const int bid = blockIdx.x;
    const int tid = threadIdx.x;

    if (bid < EMB_BLKS) {
        const int K1 = KPS, N = KPS;
        __shared__ float As[16][64];
        __shared__ float Bs[16][64];
        const int m0 = (bid >> 2) * 64;
        const int n0 = (bid & 3) * 64;
        const int ty = tid >> 4, tx = tid & 15;
        float acc[4][4];
#pragma unroll
        for (int i = 0; i < 4; i++)
#pragma unroll
            for (int j = 0; j < 4; j++) acc[i][j] = 0.0f;

        const int lrow = tid >> 2, lcol4 = (tid & 3) * 4;
        float4 av = *(const float4*)(P.embA + (size_t)(m0 + lrow) * K1 + lcol4);
        float4 wv = *(const float4*)(P.embW + (size_t)(n0 + lrow) * K1 + lcol4);

        for (int k0 = 0; k0 < K1; k0 += 16) {
            As[lcol4 + 0][lrow] = av.x; As[lcol4 + 1][lrow] = av.y;
            As[lcol4 + 2][lrow] = av.z; As[lcol4 + 3][lrow] = av.w;
            Bs[lcol4 + 0][lrow] = wv.x; Bs[lcol4 + 1][lrow] = wv.y;
            Bs[lcol4 + 2][lrow] = wv.z; Bs[lcol4 + 3][lrow] = wv.w;
            __syncthreads();
            if (k0 + 16 < K1) {
                av = *(const float4*)(P.embA + (size_t)(m0 + lrow) * K1 + k0 + 16 + lcol4);
                wv = *(const float4*)(P.embW + (size_t)(n0 + lrow) * K1 + k0 + 16 + lcol4);
            }
#pragma unroll
            for (int k = 0; k < 16; k++) {
                float ar[4], br[4];
#pragma unroll
                for (int i = 0; i < 4; i++) ar[i] = As[k][ty * 4 + i];
#pragma unroll
                for (int j = 0; j < 4; j++) br[j] = Bs[k][tx * 4 + j];
#pragma unroll
                for (int i = 0; i < 4; i++)
#pragma unroll
                    for (int j = 0; j < 4; j++)
                        acc[i][j] = fmaf(ar[i], br[j], acc[i][j]);
            }
            __syncthreads();
        }
#pragma unroll
        for (int i = 0; i < 4; i++) {
            int m = m0 + ty * 4 + i;
            int n = n0 + tx * 4;
#pragma unroll
            for (int j = 0; j < 4; j++)
                P.embC[(size_t)m * N + n + j] = __float2half_rn(acc[i][j] + P.embBias[n + j]);
        }
    } else if (bid < EMB_BLKS + CVT_BLKS) {
        int cb = bid - EMB_BLKS;
        int job, lb, nb;
        if (cb < CJ0_BLK) { job = 0; lb = cb; nb = CJ0_BLK; }
        else { job = 1 + (cb - CJ0_BLK) / CJB_BLK; lb = (cb - CJ0_BLK) % CJB_BLK; nb = CJB_BLK; }
        const float4* __restrict__ src = P.src[job];
        __half2* __restrict__ dst = P.dst[job];
        const int n4 = P.n4[job];
        const int lg = P.lgK4[job];
        const int stride = nb * blockDim.x;
        if (lg == 0) {
            for (int i = lb * blockDim.x + tid; i < n4; i += stride) {
                float4 v = src[i];
                dst[2 * i + 0] = __floats2half2_rn(v.x, v.y);
                dst[2 * i + 1] = __floats2half2_rn(v.z, v.w);
            }
        } else {
            const int msk = (1 << lg) - 1;
            for (int i = lb * blockDim.x + tid; i < n4; i += stride) {
                int n = i >> lg, kc = i & msk;
                int g = n & 3, j = n >> 2;
                float4 v = src[(((size_t)g * HID + j) << lg) + kc];
                dst[2 * i + 0] = __floats2half2_rn(v.x, v.y);
                dst[2 * i + 1] = __floats2half2_rn(v.z, v.w);
            }
        }
    } else {
        int idx = (bid - EMB_BLKS - CVT_BLKS) * 256 + tid;
        int l = idx >> 12, n = idx & 4095;
        int g = n & 3, j = n >> 2;
        P.biasp[idx] = P.bih[l][g * HID + j] + P.bhh[l][g * HID + j];
    }
}

// ===========================================================================
// Fused LSTM GEMM: 64x64 warp tiles, 4 warps (128 thr), NS=2 (64KB smem),
// 3 CTAs/SM via __launch_bounds__(128,3) (regs capped 170; frag loads
// restructured: B frags per kk [16 regs], A frag per mt [4 regs]).
// Same fp32 MMA accumulation chain as R14 -> bitwise-identical outputs.
// ===========================================================================
struct SegInfo { const __half *A, *B; int K, ldA, ldB; };
struct LstmArgs {
    SegInfo seg[2];
    const float* bias;
    const float* c_old;
    float* h_out; float* h_out2; float* c_out;
};
struct AllArgs { LstmArgs l[3]; };

__global__ void __launch_bounds__(128, 3) lstm_gemm(AllArgs args)
{
    extern __shared__ __align__(1024) char smem[];
    const LstmArgs& L = args.l[blockIdx.z];
    const int m0   = blockIdx.y * BM;
    const int n0   = blockIdx.x * BN;      // permuted-weight row base
    const int jb32 = n0 >> 2;
    const int tid  = threadIdx.x;
    const int lane = tid & 31, wid = tid >> 5;
    const int warp_m = wid & 1, warp_n = wid >> 1;   // 2 x 2
    const int wm0 = warp_m * 64, wn0 = warp_n * 64;
    const uint32_t sb = smem_u32(smem);

    const int k1 = L.seg[0].K >> 6;
    const int KT = k1 + (L.seg[1].K >> 6);

    float acc[32][4];
#pragma unroll
    for (int i = 0; i < 32; i++)
#pragma unroll
        for (int j = 0; j < 4; j++) acc[i][j] = 0.0f;

    auto load_stage = [&](int t) {
        const int s = t & 1;
        const int seg = (t >= k1) ? 1 : 0;
        const int k0 = (t - (seg ? k1 : 0)) << 6;
        const __half* Ap = L.seg[seg].A; const int ldA = L.seg[seg].ldA;
        const __half* Bp = L.seg[seg].B; const int ldB = L.seg[seg].ldB;
        const uint32_t sa = sb + s * STAGE_BYTES;
        const uint32_t sB = sa + A_BYTES;
#pragma unroll
        for (int i = 0; i < 8; i++) {
            int lin = tid + (i << 7);
            int r = lin >> 3, kc = lin & 7;
            cp_async16(sa + r * 128 + ((kc ^ (r & 7)) << 4),
                       Ap + (size_t)(m0 + r) * ldA + k0 + (kc << 3));
        }
#pragma unroll
        for (int i = 0; i < 8; i++) {
            int lin = tid + (i << 7);
            int n = lin >> 3, kc = lin & 7;
            cp_async16(sB + n * 128 + ((kc ^ (n & 7)) << 4),
                       Bp + (size_t)(n0 + n) * ldB + k0 + (kc << 3));
        }
        asm volatile("cp.async.commit_group;" ::: "memory");
    };

    load_stage(0);

    for (int t = 0; t < KT; t++) {
        asm volatile("cp.async.wait_group 0;" ::: "memory");
        __syncthreads();
        // one-stage-lookahead: buffer (t+1)&1 was fully consumed in iter t-1,
        // and the barrier above fences that consumption.
        if (t + 1 < KT) load_stage(t + 1);

        const uint32_t sa = sb + (t & 1) * STAGE_BYTES;
        const uint32_t sB = sa + A_BYTES;
#pragma unroll
        for (int kk = 0; kk < 4; kk++) {
            uint32_t bfr[4][4];
#pragma unroll
            for (int op = 0; op < 4; op++) {
                int n = wn0 + op * 16 + ((lane >> 4) << 3) + (lane & 7);
                int kc = kk * 2 + ((lane >> 3) & 1);
                ldsm_x4(bfr[op], sB + n * 128 + ((kc ^ (n & 7)) << 4));
            }
#pragma unroll
            for (int mt = 0; mt < 4; mt++) {
                uint32_t afr[4];
                int row = wm0 + mt * 16 + (lane & 15);
                int kc = kk * 2 + (lane >> 4);
                ldsm_x4(afr, sa + row * 128 + ((kc ^ (row & 7)) << 4));
#pragma unroll
                for (int op = 0; op < 4; op++) {
                    mma16816(acc[mt * 8 + op * 2 + 0], afr, bfr[op][0], bfr[op][1]);
                    mma16816(acc[mt * 8 + op * 2 + 1], afr, bfr[op][2], bfr[op][3]);
                }
            }
        }
    }

    // ---- fused LSTM epilogue (fast activations; R14 numerics) ----
    const float* __restrict__ bias = L.bias;
    const float* __restrict__ cold = L.c_old;
    const int qid = lane & 3;
#pragma unroll
    for (int mt = 0; mt < 4; mt++) {
#pragma unroll
        for (int oct = 0; oct < 8; oct++) {
            float c0 = acc[mt * 8 + oct][0], c1 = acc[mt * 8 + oct][1];
            float c2 = acc[mt * 8 + oct][2], c3 = acc[mt * 8 + oct][3];
            float o0 = __shfl_xor_sync(0xffffffffu, c0, 1);
            float o1 = __shfl_xor_sync(0xffffffffu, c1, 1);
            float o2 = __shfl_xor_sync(0xffffffffu, c2, 1);
            float o3 = __shfl_xor_sync(0xffffffffu, c3, 1);
            float gi, gf, gg, go;
            int r;
            if ((lane & 1) == 0) {      // even lane: owns (i,f), receives (g,o); row+8
                gi = c2; gf = c3; gg = o2; go = o3;
                r = wm0 + mt * 16 + (lane >> 2) + 8;
            } else {                    // odd lane: owns (g,o), receives (i,f); row
                gi = o0; gf = o1; gg = c0; go = c1;
                r = wm0 + mt * 16 + (lane >> 2);
            }
            const int j = jb32 + warp_n * 16 + oct * 2 + (qid >> 1);
            const float4 bb = *(const float4*)(bias + 4 * j);
            gi = fast_sigmoid(gi + bb.x);
            gf = fast_sigmoid(gf + bb.y);
            gg = fast_tanh(gg + bb.z);
            go = fast_sigmoid(go + bb.w);
            const size_t idx = (size_t)(m0 + r) * HID + j;
            float cn = gf * cold[idx] + gi * gg;
            float hn = go * fast_tanh(cn);
            L.c_out[idx] = cn;
            L.h_out[idx] = hn;
            if (L.h_out2) L.h_out2[idx] = hn;
        }
    }
}

// ===========================================================================
extern "C" void kernel_launch(void* const* d_in, const int* in_sizes, int n_in,
                              void* d_out, int out_size)
{
    const float* kps   = (const float*)d_in[0];
    const float* h0    = (const float*)d_in[1];
    const float* h1    = (const float*)d_in[2];
    const float* h2    = (const float*)d_in[3];
    const float* c0    = (const float*)d_in[4];
    const float* c1    = (const float*)d_in[5];
    const float* c2    = (const float*)d_in[6];
    const float* W_emb = (const float*)d_in[7];
    const float* b_emb = (const float*)d_in[8];
    const float* w_ih1 = (const float*)d_in[9];
    const float* w_hh1 = (const float*)d_in[10];
    const float* b_ih1 = (const float*)d_in[11];
    const float* b_hh1 = (const float*)d_in[12];
    const float* w_ih2 = (const float*)d_in[13];
    const float* w_hh2 = (const float*)d_in[14];
    const float* b_ih2 = (const float*)d_in[15];
    const float* b_hh2 = (const float*)d_in[16];
    const float* w_ih3 = (const float*)d_in[17];
    const float* w_hh3 = (const float*)d_in[18];
    const float* b_ih3 = (const float*)d_in[19];
    const float* b_hh3 = (const float*)d_in[20];

    float* out = (float*)d_out;
    const size_t S = (size_t)BATCH * HID;
    float* out_h2n_a = out + 0 * S;
    float* out_h0n   = out + 1 * S;
    float* out_h1n   = out + 2 * S;
    float* out_h2n_b = out + 3 * S;
    float* out_c0n   = out + 4 * S;
    float* out_c1n   = out + 5 * S;
    float* out_c2n   = out + 6 * S;

    __half* hp = nullptr;
    float* biasp = nullptr;
    cudaGetSymbolAddress((void**)&hp, g_fp16);
    cudaGetSymbolAddress((void**)&biasp, g_bias_perm);

    PrepArgs P;
    P.src[0] = (const float4*)w_ih1; P.dst[0] = (__half2*)(hp + O_WIH1); P.n4[0] = (G4H * KPS) / 4; P.lgK4[0] = 6;
    P.src[1] = (const float4*)w_hh1; P.dst[1] = (__half2*)(hp + O_WHH1); P.n4[1] = (G4H * HID) / 4; P.lgK4[1] = 8;
    P.src[2] = (const float4*)w_ih2; P.dst[2] = (__half2*)(hp + O_WIH2); P.n4[2] = (G4H * HID) / 4; P.lgK4[2] = 8;
    P.src[3] = (const float4*)w_hh2; P.dst[3] = (__half2*)(hp + O_WHH2); P.n4[3] = (G4H * HID) / 4; P.lgK4[3] = 8;
    P.src[4] = (const float4*)w_ih3; P.dst[4] = (__half2*)(hp + O_WIH3); P.n4[4] = (G4H * HID) / 4; P.lgK4[4] = 8;
    P.src[5] = (const float4*)w_hh3; P.dst[5] = (__half2*)(hp + O_WHH3); P.n4[5] = (G4H * HID) / 4; P.lgK4[5] = 8;
    P.src[6] = (const float4*)h0;    P.dst[6] = (__half2*)(hp + O_H0);   P.n4[6] = (BATCH * HID) / 4; P.lgK4[6] = 0;
    P.src[7] = (const float4*)h1;    P.dst[7] = (__half2*)(hp + O_H1);   P.n4[7] = (BATCH * HID) / 4; P.lgK4[7] = 0;
    P.src[8] = (const float4*)h2;    P.dst[8] = (__half2*)(hp + O_H2);   P.n4[8] = (BATCH * HID) / 4; P.lgK4[8] = 0;
    P.bih[0] = b_ih1; P.bhh[0] = b_hh1;
    P.bih[1] = b_ih2; P.bhh[1] = b_hh2;
    P.bih[2] = b_ih3; P.bhh[2] = b_hh3;
    P.biasp = biasp;
    P.embA = kps; P.embW = W_emb; P.embBias = b_emb; P.embC = hp + O_X;
    k_prep<<<PREP_GRID, 256>>>(P);

    AllArgs A;
    {   // LSTM1: x@wih1^T + h0@whh1^T
        LstmArgs& L = A.l[0];
        L.seg[0] = { hp + O_X,  hp + O_WIH1, KPS, KPS, KPS };
        L.seg[1] = { hp + O_H0, hp + O_WHH1, HID, HID, HID };
        L.bias = biasp + 0 * G4H; L.c_old = c0;
        L.h_out = out_h0n; L.h_out2 = nullptr; L.c_out = out_c0n;
    }
    {   // LSTM2: h0@wih2^T + h1@whh2^T (old h0 per reference)
        LstmArgs& L = A.l[1];
        L.seg[0] = { hp + O_H0, hp + O_WIH2, HID, HID, HID };
        L.seg[1] = { hp + O_H1, hp + O_WHH2, HID, HID, HID };
        L.bias = biasp + 1 * G4H; L.c_old = c1;
        L.h_out = out_h1n; L.h_out2 = nullptr; L.c_out = out_c1n;
    }
    {   // LSTM3: h1@wih3^T + h2@whh3^T (old h1 per reference)
        LstmArgs& L = A.l[2];
        L.seg[0] = { hp + O_H1, hp + O_WIH3, HID, HID, HID };
        L.seg[1] = { hp + O_H2, hp + O_WHH3, HID, HID, HID };
        L.bias = biasp + 2 * G4H; L.c_old = c2;
        L.h_out = out_h2n_a; L.h_out2 = out_h2n_b; L.c_out = out_c2n;
    }

    cudaFuncSetAttribute(lstm_gemm, cudaFuncAttributeMaxDynamicSharedMemorySize, SMEM_SZ);
    lstm_gemm<<<dim3(G4H / BN, BATCH / BM, 3), 128, SMEM_SZ>>>(A);
}